// round 9
// baseline (speedup 1.0000x reference)
#include <cuda_runtime.h>
#include <cuda_bf16.h>
#include <math.h>
#include <stdint.h>

// Problem constants
#define B       32
#define D       1024
#define VOCAB   50257
#define SEQ     128

// Fused kernel tiling (mma.sync m16n8k8 tf32; A = W1 (M=vocab), B = h)
#define VBLK    384                        // vocab cols per CTA
#define NBLK    131                        // ceil(50257/384)
#define LSS     385                        // logits smem stride (padded)
#define GT      512                        // threads (16 warps)
#define SK      16                         // k rows per stage
#define NSTG    (D / SK)                   // 64 stages
#define DEPTH   3                          // cp.async pipeline depth
#define ROWP    392                        // padded W1 smem row (floats)
#define CPR     97                         // 16B chunks per W1 row
#define HPITCH  1028                       // padded h/z smem row (floats)
#define HBYTES  (B * HPITCH * 4)           // 131584
#define BSTAGE  (SK * ROWP * 4)            // 25088
#define SMEM_DYN (HBYTES + DEPTH * BSTAGE) // 206848 < 227KB

typedef unsigned long long ull;

// ---------------- device scratch ----------------
__device__ __align__(16) float g_h[B * D];     // h, tf32-rounded
__device__ float g_pmax[NBLK * B];
__device__ float g_psum[NBLK * B];
__device__ float g_pg[NBLK];
__device__ int   g_lab64;
__device__ int   g_ctr;                        // finalize ticket
__device__ int   g_bar;                        // grid barrier counter

// ---------------- helpers ----------------
__device__ __forceinline__ uint32_t smem_u32(const void* p) {
    uint32_t a;
    asm("{ .reg .u64 t; cvta.to.shared.u64 t, %1; cvt.u32.u64 %0, t; }"
        : "=r"(a) : "l"(p));
    return a;
}
__device__ __forceinline__ uint32_t cvt_tf32(float f) {
    uint32_t r; asm("cvt.rna.tf32.f32 %0, %1;" : "=r"(r) : "f"(f)); return r;
}
__device__ __forceinline__ float lds_f(uint32_t a) {
    float v; asm volatile("ld.shared.f32 %0, [%1];" : "=f"(v) : "r"(a)); return v;
}
__device__ __forceinline__ void mma_tf32(float d[4], const uint32_t a[4],
                                         uint32_t b0, uint32_t b1) {
    asm volatile(
        "mma.sync.aligned.m16n8k8.row.col.f32.tf32.tf32.f32 "
        "{%0,%1,%2,%3}, {%4,%5,%6,%7}, {%8,%9}, {%0,%1,%2,%3};"
        : "+f"(d[0]), "+f"(d[1]), "+f"(d[2]), "+f"(d[3])
        : "r"(a[0]), "r"(a[1]), "r"(a[2]), "r"(a[3]), "r"(b0), "r"(b1));
}
__device__ __forceinline__ void cp16(uint32_t dst, const void* src) {
    asm volatile("cp.async.cg.shared.global [%0], [%1], 16;"
                 :: "r"(dst), "l"(src));
}

// W1 row k is 4B-aligned only; VOCAB % 4 == 1 -> misalign of (k*VOCAB+vbase)
// is (k+vbase)&3. cp.async 16B from aligned-down addr into padded row.
__device__ __forceinline__ void load_bstage(uint32_t bsm, int buf, int s,
                                            const float* __restrict__ W1,
                                            int vbase, int t)
{
    const uint32_t sb = bsm + (uint32_t)buf * BSTAGE;
    const long maxe = (long)D * VOCAB - 4;
    for (int i = t; i < SK * CPR; i += GT) {
        int r = i / CPR, c = i - r * CPR;
        long e0 = (((long)(s * SK + r) * VOCAB + vbase) & ~3L) + (long)c * 4;
        if (e0 > maxe) e0 = maxe;
        cp16(sb + (uint32_t)(r * ROWP + c * 4) * 4, W1 + e0);
    }
}

// ======================= the single fused kernel ==========================
__global__ __launch_bounds__(GT, 1) void fused_kernel(
    const float* __restrict__ z,  const float* __restrict__ W0,
    const float* __restrict__ b0v, const float* __restrict__ W1,
    const float* __restrict__ b1, const void* __restrict__ labels,
    float* __restrict__ out)
{
    extern __shared__ __align__(1024) char dyn[];
    __shared__ float red[GT];
    __shared__ int   is_last;
    __shared__ int   s_bad;
    __shared__ float s_lse[B];

    const int t    = threadIdx.x;
    const int wid  = t >> 5, lane = t & 31;
    const int g    = lane >> 2;          // MMA groupID
    const int tig  = lane & 3;           // thread-in-group
    const int bid  = blockIdx.x;
    const int vbase = bid * VBLK;
    const uint32_t hsm = smem_u32(dyn);
    const uint32_t bsm = hsm + HBYTES;

    // ---- issue z load (group 0), then W1 stages 0..2 (groups 1..3) ----
    for (int i = t; i < B * (D / 4); i += GT) {
        int bb = i >> 8, c = i & 255;
        cp16(hsm + (uint32_t)(bb * HPITCH + c * 4) * 4, z + bb * D + c * 4);
    }
    asm volatile("cp.async.commit_group;" ::: "memory");
    load_bstage(bsm, 0, 0, W1, vbase, t);
    asm volatile("cp.async.commit_group;" ::: "memory");
    load_bstage(bsm, 1, 1, W1, vbase, t);
    asm volatile("cp.async.commit_group;" ::: "memory");
    load_bstage(bsm, 2, 2, W1, vbase, t);
    asm volatile("cp.async.commit_group;" ::: "memory");
    asm volatile("cp.async.wait_group 3;" ::: "memory");   // z landed
    __syncthreads();

    // ---- phase A: GEMM1 + bias + GELU -> g_h (tf32-rounded) ----
    if (bid < 128) {
        const int jj  = t & 7;
        const int bb  = (t >> 3) & 31;
        const int kg2 = t >> 8;                 // split-k half
        const int j   = bid * 8 + jj;
        const float* w = W0 + (size_t)(kg2 * 512) * D + j;
        const uint32_t zb = hsm + (uint32_t)(bb * HPITCH + kg2 * 512) * 4;
        float a0 = 0.f, a1 = 0.f, a2 = 0.f, a3 = 0.f;
        #pragma unroll 4
        for (int k = 0; k < 512; k += 4) {
            a0 += lds_f(zb + (k    ) * 4) * w[(size_t)(k    ) * D];
            a1 += lds_f(zb + (k + 1) * 4) * w[(size_t)(k + 1) * D];
            a2 += lds_f(zb + (k + 2) * 4) * w[(size_t)(k + 2) * D];
            a3 += lds_f(zb + (k + 3) * 4) * w[(size_t)(k + 3) * D];
        }
        float s = (a0 + a1) + (a2 + a3);
        if (kg2 == 1) red[t - 256] = s;
        __syncthreads();
        if (kg2 == 0) {
            s += red[t] + b0v[j];
            float gel = 0.5f * s * (1.0f + erff(s * 0.70710678118654752f));
            g_h[bb * D + j] = __uint_as_float(cvt_tf32(gel));
        }
    } else if (bid == 128) {
        // label dtype probe (int64 vs int32, JAX x64-off gives int32)
        if (t == 0) s_bad = 0;
        __syncthreads();
        const long long* lab = (const long long*)labels;
        int bad = 0;
        for (int i = t; i < 2048; i += GT) {
            long long v = lab[i];
            if (v < 0 || v >= (long long)VOCAB) bad = 1;
        }
        if (bad) s_bad = 1;
        __syncthreads();
        if (t == 0) g_lab64 = s_bad ? 0 : 1;
    }

    // ---- grid-wide barrier (all 131 CTAs resident: 1 CTA/SM, one wave) ----
    __threadfence();
    __syncthreads();
    if (t == 0) {
        atomicAdd(&g_bar, 1);
        while (*(volatile int*)&g_bar < NBLK) __nanosleep(64);
    }
    __syncthreads();
    __threadfence();

    // ---- broadcast h into smem (overwrites z region), group 4 ----
    for (int i = t; i < B * (D / 4); i += GT) {
        int bb = i >> 8, c = i & 255;
        cp16(hsm + (uint32_t)(bb * HPITCH + c * 4) * 4, g_h + bb * D + c * 4);
    }
    asm volatile("cp.async.commit_group;" ::: "memory");

    // ---- GEMM2 mainloop: 16 warps = 8 vocab-groups x 2 k8-halves ----
    const int wv  = wid & 7;             // vocab group
    const int kg  = wid >> 3;            // k8 half within stage
    const int n0w = wv * 48;
    const int kb  = kg * 8;

    float acc[3][4][4];
    #pragma unroll
    for (int mt = 0; mt < 3; ++mt)
        #pragma unroll
        for (int nt = 0; nt < 4; ++nt)
            #pragma unroll
            for (int r = 0; r < 4; ++r) acc[mt][nt][r] = 0.f;

    for (int s = 0; s < NSTG; ++s) {
        if (s == 0) asm volatile("cp.async.wait_group 0;" ::: "memory");
        else        asm volatile("cp.async.wait_group 2;" ::: "memory");
        __syncthreads();
        const uint32_t sb = bsm + (uint32_t)(s % DEPTH) * BSTAGE;
        const int kabs = s * SK + kb;
        // A fragments from W1 smem [k][n]
        const int sh = (kabs + tig + vbase) & 3;
        const uint32_t r0 = sb + (uint32_t)((kb + tig)     * ROWP + sh) * 4;
        const uint32_t r1 = sb + (uint32_t)((kb + tig + 4) * ROWP + sh) * 4;
        uint32_t a[3][4];
        #pragma unroll
        for (int mt = 0; mt < 3; ++mt) {
            const uint32_t co = (uint32_t)(n0w + mt * 16 + g) * 4;
            a[mt][0] = cvt_tf32(lds_f(r0 + co));
            a[mt][1] = cvt_tf32(lds_f(r0 + co + 32));
            a[mt][2] = cvt_tf32(lds_f(r1 + co));
            a[mt][3] = cvt_tf32(lds_f(r1 + co + 32));
        }
        // B fragments from h smem [b][k]
        uint32_t b0f[4], b1f[4];
        #pragma unroll
        for (int nt = 0; nt < 4; ++nt) {
            const uint32_t hr = hsm +
                (uint32_t)((nt * 8 + g) * HPITCH + kabs + tig) * 4;
            b0f[nt] = __float_as_uint(lds_f(hr));
            b1f[nt] = __float_as_uint(lds_f(hr + 16));
        }
        #pragma unroll
        for (int mt = 0; mt < 3; ++mt)
            #pragma unroll
            for (int nt = 0; nt < 4; ++nt)
                mma_tf32(acc[mt][nt], a[mt], b0f[nt], b1f[nt]);
        __syncthreads();
        if (s + DEPTH < NSTG)
            load_bstage(bsm, s % DEPTH, s + DEPTH, W1, vbase, t);
        asm volatile("cp.async.commit_group;" ::: "memory");
    }
    asm volatile("cp.async.wait_group 0;" ::: "memory");
    __syncthreads();

    // ---- epilogue: merge split-k pairs into smem logits ----
    float* Ls = (float*)dyn;                      // [32][LSS]
    if (kg == 0) {
        #pragma unroll
        for (int mt = 0; mt < 3; ++mt) {
            const int vloc0 = n0w + mt * 16 + g;
            const int v0 = vbase + vloc0, v8 = v0 + 8;
            const float bi0 = b1[v0 < VOCAB ? v0 : (VOCAB - 1)];
            const float bi8 = b1[v8 < VOCAB ? v8 : (VOCAB - 1)];
            #pragma unroll
            for (int nt = 0; nt < 4; ++nt) {
                const int bb = nt * 8 + 2 * tig;
                Ls[bb * LSS + vloc0]           = (v0 < VOCAB) ? acc[mt][nt][0] + bi0 : -1e30f;
                Ls[(bb + 1) * LSS + vloc0]     = (v0 < VOCAB) ? acc[mt][nt][1] + bi0 : -1e30f;
                Ls[bb * LSS + vloc0 + 8]       = (v8 < VOCAB) ? acc[mt][nt][2] + bi8 : -1e30f;
                Ls[(bb + 1) * LSS + vloc0 + 8] = (v8 < VOCAB) ? acc[mt][nt][3] + bi8 : -1e30f;
            }
        }
    }
    __syncthreads();
    if (kg == 1) {
        // masked cells hold -1e30; adding a bounded partial is absorbed.
        #pragma unroll
        for (int mt = 0; mt < 3; ++mt) {
            const int vloc0 = n0w + mt * 16 + g;
            #pragma unroll
            for (int nt = 0; nt < 4; ++nt) {
                const int bb = nt * 8 + 2 * tig;
                Ls[bb * LSS + vloc0]           += acc[mt][nt][0];
                Ls[(bb + 1) * LSS + vloc0]     += acc[mt][nt][1];
                Ls[bb * LSS + vloc0 + 8]       += acc[mt][nt][2];
                Ls[(bb + 1) * LSS + vloc0 + 8] += acc[mt][nt][3];
            }
        }
    }
    __syncthreads();

    // ---- label gather ----
    const int lab64 = g_lab64;
    const long long* lab_ll = (const long long*)labels;
    const int*       lab_i  = (const int*)labels;
    float gg = 0.f;
    for (int i = t; i < B * SEQ; i += GT) {
        int bb = i >> 7;
        int lab = lab64 ? (int)lab_ll[i] : lab_i[i];
        int rel = lab - vbase;
        if (rel >= 0 && rel < VBLK) gg += Ls[bb * LSS + rel];
    }
    red[t] = gg;
    __syncthreads();
    for (int off = GT / 2; off; off >>= 1) {
        if (t < off) red[t] += red[t + off];
        __syncthreads();
    }
    if (t == 0) g_pg[bid] = red[0];

    // ---- per-b partial (max, sumexp) over this block's 384 cols ----
    #pragma unroll
    for (int bi = 0; bi < 2; ++bi) {
        const int bb = wid * 2 + bi;
        float m = -1e30f;
        for (int vv = lane; vv < VBLK; vv += 32)
            m = fmaxf(m, Ls[bb * LSS + vv]);
        #pragma unroll
        for (int o = 16; o; o >>= 1)
            m = fmaxf(m, __shfl_xor_sync(0xffffffffu, m, o));
        float sum = 0.f;
        for (int vv = lane; vv < VBLK; vv += 32)
            sum += __expf(Ls[bb * LSS + vv] - m);
        #pragma unroll
        for (int o = 16; o; o >>= 1)
            sum += __shfl_xor_sync(0xffffffffu, sum, o);
        if (lane == 0) {
            g_pmax[bid * B + bb] = m;
            g_psum[bid * B + bb] = sum;
        }
    }

    // ---- fused finalize: last CTA reduces all partials ----
    __threadfence();
    __syncthreads();
    if (t == 0) {
        int old = atomicAdd(&g_ctr, 1);
        is_last = (old == NBLK - 1);
    }
    __syncthreads();
    if (!is_last) return;
    __threadfence();

    #pragma unroll
    for (int bi = 0; bi < 2; ++bi) {
        const int bb = wid * 2 + bi;
        float m = -1e30f;
        for (int i = lane; i < NBLK; i += 32)
            m = fmaxf(m, g_pmax[i * B + bb]);
        #pragma unroll
        for (int o = 16; o; o >>= 1)
            m = fmaxf(m, __shfl_xor_sync(0xffffffffu, m, o));
        float sum = 0.f;
        for (int i = lane; i < NBLK; i += 32)
            sum += g_psum[i * B + bb] * __expf(g_pmax[i * B + bb] - m);
        #pragma unroll
        for (int o = 16; o; o >>= 1)
            sum += __shfl_xor_sync(0xffffffffu, sum, o);
        if (lane == 0) s_lse[bb] = m + logf(sum);
    }
    red[t] = (t < NBLK) ? g_pg[t] : 0.f;
    __syncthreads();
    for (int off = GT / 2; off; off >>= 1) {
        if (t < off) red[t] += red[t + off];
        __syncthreads();
    }
    if (t == 0) {
        float L = 0.f;
        #pragma unroll
        for (int bb = 0; bb < B; ++bb) L += s_lse[bb];
        out[0] = L / (float)B - red[0] / (float)(B * SEQ);
        g_ctr = 0;                       // reset for graph replay
        g_bar = 0;
    }
}

// =========================== launch ======================================
extern "C" void kernel_launch(void* const* d_in, const int* in_sizes, int n_in,
                              void* d_out, int out_size)
{
    const float* z = nullptr; const void* labels = nullptr;
    const float* W0 = nullptr; const float* b0 = nullptr;
    const float* W1 = nullptr; const float* b1 = nullptr;
    for (int i = 0; i < n_in; ++i) {
        switch (in_sizes[i]) {
            case B * D:        z      = (const float*)d_in[i];      break;
            case B * SEQ:      labels = d_in[i];                    break;
            case D * D:        W0     = (const float*)d_in[i];      break;
            case D:            b0     = (const float*)d_in[i];      break;
            case D * VOCAB:    W1     = (const float*)d_in[i];      break;
            case VOCAB:        b1     = (const float*)d_in[i];      break;
            default: break;
        }
    }

    static bool attr_done = false;
    if (!attr_done) {
        cudaFuncSetAttribute(fused_kernel,
                             cudaFuncAttributeMaxDynamicSharedMemorySize,
                             SMEM_DYN);
        attr_done = true;
    }

    fused_kernel<<<NBLK, GT, SMEM_DYN>>>(z, W0, b0, W1, b1, labels,
                                         (float*)d_out);
}

// round 10
// speedup vs baseline: 1.0548x; 1.0548x over previous
#include <cuda_runtime.h>
#include <cuda_bf16.h>
#include <math.h>
#include <stdint.h>

// Problem constants
#define B       32
#define D       1024
#define VOCAB   50257
#define SEQ     128

// Fused kernel tiling (mma.sync m16n8k8 tf32; A = W1 (M=vocab), B = h)
#define VBLK    384                        // vocab cols per CTA
#define NBLK    131                        // ceil(50257/384)
#define LSS     385                        // logits smem stride (padded)
#define GT      512                        // threads (16 warps)
#define SK      16                         // k rows per stage
#define NSTG    (D / SK)                   // 64 stages
#define DEPTH   3                          // TMA pipeline depth
#define ROWP    392                        // padded W1 smem row (floats)
#define HPITCH  1028                       // padded h/z smem row (floats)
#define HBYTES  (B * HPITCH * 4)           // 131584
#define BSTAGE  (SK * ROWP * 4)            // 25088
#define SMEM_DYN (HBYTES + DEPTH * BSTAGE) // 206848 < 227KB

typedef unsigned long long ull;

// ---------------- device scratch ----------------
__device__ __align__(16) float g_h[B * D];     // h, tf32-rounded
__device__ float g_pmax[NBLK * B];
__device__ float g_psum[NBLK * B];
__device__ float g_pg[NBLK];
__device__ int   g_lab64;
__device__ int   g_ctr;                        // finalize ticket
__device__ int   g_bar;                        // grid barrier counter

// ---------------- helpers ----------------
__device__ __forceinline__ uint32_t smem_u32(const void* p) {
    uint32_t a;
    asm("{ .reg .u64 t; cvta.to.shared.u64 t, %1; cvt.u32.u64 %0, t; }"
        : "=r"(a) : "l"(p));
    return a;
}
__device__ __forceinline__ uint32_t cvt_tf32(float f) {
    uint32_t r; asm("cvt.rna.tf32.f32 %0, %1;" : "=r"(r) : "f"(f)); return r;
}
__device__ __forceinline__ float lds_f(uint32_t a) {
    float v; asm volatile("ld.shared.f32 %0, [%1];" : "=f"(v) : "r"(a)); return v;
}
__device__ __forceinline__ void mma_tf32(float d[4], const uint32_t a[4],
                                         uint32_t b0, uint32_t b1) {
    asm volatile(
        "mma.sync.aligned.m16n8k8.row.col.f32.tf32.tf32.f32 "
        "{%0,%1,%2,%3}, {%4,%5,%6,%7}, {%8,%9}, {%0,%1,%2,%3};"
        : "+f"(d[0]), "+f"(d[1]), "+f"(d[2]), "+f"(d[3])
        : "r"(a[0]), "r"(a[1]), "r"(a[2]), "r"(a[3]), "r"(b0), "r"(b1));
}
__device__ __forceinline__ void cp16(uint32_t dst, const void* src) {
    asm volatile("cp.async.cg.shared.global [%0], [%1], 16;"
                 :: "r"(dst), "l"(src));
}

#define MBAR_INIT(mb, n) \
    asm volatile("mbarrier.init.shared.b64 [%0], %1;" \
                 :: "r"(mb), "r"((uint32_t)(n)) : "memory")
#define FENCE_ASYNC() asm volatile("fence.proxy.async.shared::cta;" ::: "memory")
#define MBAR_WAIT(mb, ph) do {                                              \
    uint32_t _m = (mb), _p = (ph), _d;                                      \
    asm volatile("{\n\t.reg .pred p;\n\t"                                   \
        "mbarrier.try_wait.parity.acquire.cta.shared::cta.b64 p, [%1], %2;\n\t" \
        "selp.b32 %0, 1, 0, p;\n\t}" : "=r"(_d) : "r"(_m), "r"(_p) : "memory"); \
    if (!_d) {                                                              \
        asm volatile("{\n\t.reg .pred P1;\n\tWL_%=:\n\t"                    \
            "mbarrier.try_wait.parity.acquire.cta.shared::cta.b64 P1, [%0], %1, 0x989680;\n\t" \
            "@P1 bra.uni WD_%=;\n\tbra.uni WL_%=;\n\tWD_%=:\n\t}"           \
            :: "r"(_m), "r"(_p) : "memory");                                \
    }                                                                       \
} while (0)

// One TMA bulk copy per W1 row: 16 ops/stage (vs 1552 cp.asyncs).
// W1 row k is 4B-aligned; VOCAB%4==1 -> misalign of (k*VOCAB+vbase) is
// (k+vbase)&3; load from aligned-down addr, shift at fragment-read time.
// Tail row (only global k=1023 of CTA 130) clamps size to stay in-bounds;
// trailing smem bytes there hold finite W1 data from a prior stage pass.
__device__ __forceinline__ void tma_load_stage(uint32_t bsm, uint32_t mbb,
                                               int s, const float* __restrict__ W1,
                                               int vbase)
{
    const uint32_t sb = bsm + (uint32_t)(s % DEPTH) * BSTAGE;
    const uint32_t mb = mbb + (uint32_t)(s % DEPTH) * 8;
    const long endi = (long)D * VOCAB;
    long e0[SK]; uint32_t sz[SK]; uint32_t total = 0;
    #pragma unroll
    for (int r = 0; r < SK; ++r) {
        e0[r] = ((long)(s * SK + r) * VOCAB + vbase) & ~3L;
        long rem = endi - e0[r];                       // floats available
        sz[r] = (rem >= (long)ROWP) ? (uint32_t)(ROWP * 4)
                                    : (((uint32_t)rem * 4u) & ~15u);
        total += sz[r];
    }
    asm volatile("mbarrier.arrive.expect_tx.shared.b64 _, [%0], %1;"
                 :: "r"(mb), "r"(total) : "memory");
    #pragma unroll
    for (int r = 0; r < SK; ++r) {
        asm volatile(
            "cp.async.bulk.shared::cta.global.mbarrier::complete_tx::bytes "
            "[%0], [%1], %2, [%3];"
            :: "r"(sb + (uint32_t)(r * ROWP * 4)), "l"(W1 + e0[r]),
               "r"(sz[r]), "r"(mb) : "memory");
    }
}

// ======================= the single fused kernel ==========================
__global__ __launch_bounds__(GT, 1) void fused_kernel(
    const float* __restrict__ z,  const float* __restrict__ W0,
    const float* __restrict__ b0v, const float* __restrict__ W1,
    const float* __restrict__ b1, const void* __restrict__ labels,
    float* __restrict__ out)
{
    extern __shared__ __align__(1024) char dyn[];
    __shared__ __align__(8) ull s_mbar[DEPTH];
    __shared__ float red[GT];
    __shared__ int   is_last;
    __shared__ int   s_bad;
    __shared__ float s_lse[B];

    const int t    = threadIdx.x;
    const int wid  = t >> 5, lane = t & 31;
    const int g    = lane >> 2;          // MMA groupID
    const int tig  = lane & 3;           // thread-in-group
    const int bid  = blockIdx.x;
    const int vbase = bid * VBLK;
    const uint32_t hsm = smem_u32(dyn);
    const uint32_t bsm = hsm + HBYTES;
    const uint32_t mbb = smem_u32(s_mbar);

    // ---- init mbarriers, start z load ----
    if (t == 0) {
        #pragma unroll
        for (int d = 0; d < DEPTH; ++d) MBAR_INIT(mbb + d * 8, 1);
    }
    for (int i = t; i < B * (D / 4); i += GT) {
        int bb = i >> 8, c = i & 255;
        cp16(hsm + (uint32_t)(bb * HPITCH + c * 4) * 4, z + bb * D + c * 4);
    }
    asm volatile("cp.async.commit_group;" ::: "memory");
    __syncthreads();                     // mbarrier init visible to all
    if (t == 0) {                        // kick off W1 stages 0..2 via TMA
        FENCE_ASYNC();
        tma_load_stage(bsm, mbb, 0, W1, vbase);
        tma_load_stage(bsm, mbb, 1, W1, vbase);
        tma_load_stage(bsm, mbb, 2, W1, vbase);
    }
    asm volatile("cp.async.wait_group 0;" ::: "memory");   // z landed
    __syncthreads();

    // ---- phase A: GEMM1 + bias + GELU -> g_h (tf32-rounded) ----
    if (bid < 128) {
        const int jj  = t & 7;
        const int bb  = (t >> 3) & 31;
        const int kg2 = t >> 8;                 // split-k half
        const int j   = bid * 8 + jj;
        const float* w = W0 + (size_t)(kg2 * 512) * D + j;
        const uint32_t zb = hsm + (uint32_t)(bb * HPITCH + kg2 * 512) * 4;
        float a0 = 0.f, a1 = 0.f, a2 = 0.f, a3 = 0.f;
        #pragma unroll 4
        for (int k = 0; k < 512; k += 4) {
            a0 += lds_f(zb + (k    ) * 4) * w[(size_t)(k    ) * D];
            a1 += lds_f(zb + (k + 1) * 4) * w[(size_t)(k + 1) * D];
            a2 += lds_f(zb + (k + 2) * 4) * w[(size_t)(k + 2) * D];
            a3 += lds_f(zb + (k + 3) * 4) * w[(size_t)(k + 3) * D];
        }
        float s = (a0 + a1) + (a2 + a3);
        if (kg2 == 1) red[t - 256] = s;
        __syncthreads();
        if (kg2 == 0) {
            s += red[t] + b0v[j];
            float gel = 0.5f * s * (1.0f + erff(s * 0.70710678118654752f));
            g_h[bb * D + j] = __uint_as_float(cvt_tf32(gel));
        }
    } else if (bid == 128) {
        // label dtype probe (int64 vs int32, JAX x64-off gives int32)
        if (t == 0) s_bad = 0;
        __syncthreads();
        const long long* lab = (const long long*)labels;
        int bad = 0;
        for (int i = t; i < 2048; i += GT) {
            long long v = lab[i];
            if (v < 0 || v >= (long long)VOCAB) bad = 1;
        }
        if (bad) s_bad = 1;
        __syncthreads();
        if (t == 0) g_lab64 = s_bad ? 0 : 1;
    }

    // ---- grid-wide barrier (131 CTAs, 1/SM, one wave) ----
    __threadfence();
    __syncthreads();
    if (t == 0) {
        atomicAdd(&g_bar, 1);
        while (*(volatile int*)&g_bar < NBLK) __nanosleep(64);
    }
    __syncthreads();
    __threadfence();

    // ---- broadcast h into smem (overwrites z region) ----
    for (int i = t; i < B * (D / 4); i += GT) {
        int bb = i >> 8, c = i & 255;
        cp16(hsm + (uint32_t)(bb * HPITCH + c * 4) * 4, g_h + bb * D + c * 4);
    }
    asm volatile("cp.async.commit_group;" ::: "memory");
    asm volatile("cp.async.wait_group 0;" ::: "memory");

    // ---- GEMM2 mainloop: 16 warps = 8 vocab-groups x 2 k8-halves ----
    const int wv  = wid & 7;             // vocab group
    const int kg  = wid >> 3;            // k8 half within stage
    const int n0w = wv * 48;
    const int kb  = kg * 8;

    float acc[3][4][4];
    #pragma unroll
    for (int mt = 0; mt < 3; ++mt)
        #pragma unroll
        for (int nt = 0; nt < 4; ++nt)
            #pragma unroll
            for (int r = 0; r < 4; ++r) acc[mt][nt][r] = 0.f;

    for (int s = 0; s < NSTG; ++s) {
        MBAR_WAIT(mbb + (uint32_t)(s % DEPTH) * 8, (s / DEPTH) & 1);
        const uint32_t sb = bsm + (uint32_t)(s % DEPTH) * BSTAGE;
        const int kabs = s * SK + kb;
        // A fragments from W1 smem [k][n]
        const int sh = (kabs + tig + vbase) & 3;
        const uint32_t r0 = sb + (uint32_t)((kb + tig)     * ROWP + sh) * 4;
        const uint32_t r1 = sb + (uint32_t)((kb + tig + 4) * ROWP + sh) * 4;
        uint32_t a[3][4];
        #pragma unroll
        for (int mt = 0; mt < 3; ++mt) {
            const uint32_t co = (uint32_t)(n0w + mt * 16 + g) * 4;
            a[mt][0] = cvt_tf32(lds_f(r0 + co));
            a[mt][1] = cvt_tf32(lds_f(r0 + co + 32));
            a[mt][2] = cvt_tf32(lds_f(r1 + co));
            a[mt][3] = cvt_tf32(lds_f(r1 + co + 32));
        }
        // B fragments from h smem [b][k]
        uint32_t b0f[4], b1f[4];
        #pragma unroll
        for (int nt = 0; nt < 4; ++nt) {
            const uint32_t hr = hsm +
                (uint32_t)((nt * 8 + g) * HPITCH + kabs + tig) * 4;
            b0f[nt] = __float_as_uint(lds_f(hr));
            b1f[nt] = __float_as_uint(lds_f(hr + 16));
        }
        #pragma unroll
        for (int mt = 0; mt < 3; ++mt)
            #pragma unroll
            for (int nt = 0; nt < 4; ++nt)
                mma_tf32(acc[mt][nt], a[mt], b0f[nt], b1f[nt]);
        __syncthreads();                 // all warps done with buffer s%DEPTH
        if (t == 0 && s + DEPTH < NSTG)
            tma_load_stage(bsm, mbb, s + DEPTH, W1, vbase);
    }

    // ---- epilogue: merge split-k pairs into smem logits ----
    float* Ls = (float*)dyn;                      // [32][LSS]
    if (kg == 0) {
        #pragma unroll
        for (int mt = 0; mt < 3; ++mt) {
            const int vloc0 = n0w + mt * 16 + g;
            const int v0 = vbase + vloc0, v8 = v0 + 8;
            const float bi0 = b1[v0 < VOCAB ? v0 : (VOCAB - 1)];
            const float bi8 = b1[v8 < VOCAB ? v8 : (VOCAB - 1)];
            #pragma unroll
            for (int nt = 0; nt < 4; ++nt) {
                const int bb = nt * 8 + 2 * tig;
                Ls[bb * LSS + vloc0]           = (v0 < VOCAB) ? acc[mt][nt][0] + bi0 : -1e30f;
                Ls[(bb + 1) * LSS + vloc0]     = (v0 < VOCAB) ? acc[mt][nt][1] + bi0 : -1e30f;
                Ls[bb * LSS + vloc0 + 8]       = (v8 < VOCAB) ? acc[mt][nt][2] + bi8 : -1e30f;
                Ls[(bb + 1) * LSS + vloc0 + 8] = (v8 < VOCAB) ? acc[mt][nt][3] + bi8 : -1e30f;
            }
        }
    }
    __syncthreads();
    if (kg == 1) {
        // masked cells hold -1e30; adding a bounded partial is absorbed.
        #pragma unroll
        for (int mt = 0; mt < 3; ++mt) {
            const int vloc0 = n0w + mt * 16 + g;
            #pragma unroll
            for (int nt = 0; nt < 4; ++nt) {
                const int bb = nt * 8 + 2 * tig;
                Ls[bb * LSS + vloc0]           += acc[mt][nt][0];
                Ls[(bb + 1) * LSS + vloc0]     += acc[mt][nt][1];
                Ls[bb * LSS + vloc0 + 8]       += acc[mt][nt][2];
                Ls[(bb + 1) * LSS + vloc0 + 8] += acc[mt][nt][3];
            }
        }
    }
    __syncthreads();

    // ---- label gather ----
    const int lab64 = g_lab64;
    const long long* lab_ll = (const long long*)labels;
    const int*       lab_i  = (const int*)labels;
    float gg = 0.f;
    for (int i = t; i < B * SEQ; i += GT) {
        int bb = i >> 7;
        int lab = lab64 ? (int)lab_ll[i] : lab_i[i];
        int rel = lab - vbase;
        if (rel >= 0 && rel < VBLK) gg += Ls[bb * LSS + rel];
    }
    red[t] = gg;
    __syncthreads();
    for (int off = GT / 2; off; off >>= 1) {
        if (t < off) red[t] += red[t + off];
        __syncthreads();
    }
    if (t == 0) g_pg[bid] = red[0];

    // ---- per-b partial (max, sumexp) over this block's 384 cols ----
    #pragma unroll
    for (int bi = 0; bi < 2; ++bi) {
        const int bb = wid * 2 + bi;
        float m = -1e30f;
        for (int vv = lane; vv < VBLK; vv += 32)
            m = fmaxf(m, Ls[bb * LSS + vv]);
        #pragma unroll
        for (int o = 16; o; o >>= 1)
            m = fmaxf(m, __shfl_xor_sync(0xffffffffu, m, o));
        float sum = 0.f;
        for (int vv = lane; vv < VBLK; vv += 32)
            sum += __expf(Ls[bb * LSS + vv] - m);
        #pragma unroll
        for (int o = 16; o; o >>= 1)
            sum += __shfl_xor_sync(0xffffffffu, sum, o);
        if (lane == 0) {
            g_pmax[bid * B + bb] = m;
            g_psum[bid * B + bb] = sum;
        }
    }

    // ---- fused finalize: last CTA reduces all partials ----
    __threadfence();
    __syncthreads();
    if (t == 0) {
        int old = atomicAdd(&g_ctr, 1);
        is_last = (old == NBLK - 1);
    }
    __syncthreads();
    if (!is_last) return;
    __threadfence();

    #pragma unroll
    for (int bi = 0; bi < 2; ++bi) {
        const int bb = wid * 2 + bi;
        float m = -1e30f;
        for (int i = lane; i < NBLK; i += 32)
            m = fmaxf(m, g_pmax[i * B + bb]);
        #pragma unroll
        for (int o = 16; o; o >>= 1)
            m = fmaxf(m, __shfl_xor_sync(0xffffffffu, m, o));
        float sum = 0.f;
        for (int i = lane; i < NBLK; i += 32)
            sum += g_psum[i * B + bb] * __expf(g_pmax[i * B + bb] - m);
        #pragma unroll
        for (int o = 16; o; o >>= 1)
            sum += __shfl_xor_sync(0xffffffffu, sum, o);
        if (lane == 0) s_lse[bb] = m + logf(sum);
    }
    red[t] = (t < NBLK) ? g_pg[t] : 0.f;
    __syncthreads();
    for (int off = GT / 2; off; off >>= 1) {
        if (t < off) red[t] += red[t + off];
        __syncthreads();
    }
    if (t == 0) {
        float L = 0.f;
        #pragma unroll
        for (int bb = 0; bb < B; ++bb) L += s_lse[bb];
        out[0] = L / (float)B - red[0] / (float)(B * SEQ);
        g_ctr = 0;                       // reset for graph replay
        g_bar = 0;
    }
}

// =========================== launch ======================================
extern "C" void kernel_launch(void* const* d_in, const int* in_sizes, int n_in,
                              void* d_out, int out_size)
{
    const float* z = nullptr; const void* labels = nullptr;
    const float* W0 = nullptr; const float* b0 = nullptr;
    const float* W1 = nullptr; const float* b1 = nullptr;
    for (int i = 0; i < n_in; ++i) {
        switch (in_sizes[i]) {
            case B * D:        z      = (const float*)d_in[i];      break;
            case B * SEQ:      labels = d_in[i];                    break;
            case D * D:        W0     = (const float*)d_in[i];      break;
            case D:            b0     = (const float*)d_in[i];      break;
            case D * VOCAB:    W1     = (const float*)d_in[i];      break;
            case VOCAB:        b1     = (const float*)d_in[i];      break;
            default: break;
        }
    }

    static bool attr_done = false;
    if (!attr_done) {
        cudaFuncSetAttribute(fused_kernel,
                             cudaFuncAttributeMaxDynamicSharedMemorySize,
                             SMEM_DYN);
        attr_done = true;
    }

    fused_kernel<<<NBLK, GT, SMEM_DYN>>>(z, W0, b0, W1, b1, labels,
                                         (float*)d_out);
}